// round 14
// baseline (speedup 1.0000x reference)
#include <cuda_runtime.h>
#include <math.h>

#define Bsz 64
#define Tsz 2048
#define Dsz 256
#define Hsz 512
#define Gsz 2048
#define NB  128
#define GRP 64

typedef unsigned long long u64;

// ---- packed fp32x2 helpers (Blackwell FFMA2, PTX-only) ----
__device__ __forceinline__ u64 ffma2(u64 a, u64 b, u64 c) {
    u64 d;
    asm("fma.rn.f32x2 %0, %1, %2, %3;" : "=l"(d) : "l"(a), "l"(b), "l"(c));
    return d;
}
__device__ __forceinline__ u64 dup2(float x) {
    u64 d;
    asm("mov.b64 %0, {%1, %1};" : "=l"(d) : "r"(__float_as_uint(x)));
    return d;
}

// Scratch (device globals)
__device__ float g_xT[(size_t)Tsz * Dsz * Bsz];    // [t][k][b]  134 MB
__device__ float g_Up[64 * Hsz * 32];              // [cg][k(512)][c(32)]  4 MB
__device__ float g_Wp[64 * Dsz * 32];              // [cg][k(256)][c(32)]  2 MB
__device__ float g_h[2 * Hsz * Bsz];               // [parity][j][b]
__device__ unsigned g_cnt2[64];                    // 2 counters, 128B apart

__global__ void reset_bar_k() { if (threadIdx.x < 64) g_cnt2[threadIdx.x] = 0u; }

// x[b][t][k] -> g_xT[t][k][b]; reads L2-reused, writes coalesced in b
__global__ void transpose_x_k(const float* __restrict__ x) {
    size_t idx = (size_t)blockIdx.x * 256 + threadIdx.x;   // 2^25
    int b = (int)(idx & 63);
    int k = (int)((idx >> 6) & 255);
    int t = (int)(idx >> 14);
    g_xT[((size_t)t * Dsz + k) * Bsz + b] = x[((size_t)b * Tsz + t) * Dsz + k];
}

// g_Up[cg][k][c] = U[k][gate*512 + cg*8 + jj], c = gate*8 + jj  (32 cols per cg)
__global__ void pack_U_k(const float* __restrict__ U) {
    int idx = blockIdx.x * blockDim.x + threadIdx.x;   // 2^20 total
    int c  = idx & 31;
    int k  = (idx >> 5) & (Hsz - 1);
    int cg = idx >> 14;
    g_Up[idx] = U[k * Gsz + (c >> 3) * Hsz + cg * 8 + (c & 7)];
}

// g_Wp[cg][k][c] = W[k][gate*512 + cg*8 + jj], k in [0,256)
__global__ void pack_W_k(const float* __restrict__ W) {
    int idx = blockIdx.x * blockDim.x + threadIdx.x;   // 2^19 total
    int c  = idx & 31;
    int k  = (idx >> 5) & (Dsz - 1);
    int cg = idx >> 13;
    g_Wp[idx] = W[k * Gsz + (c >> 3) * Hsz + cg * 8 + (c & 7)];
}

// ---- dual 64-CTA group barriers: release-REDG arrive + acquire-poll wait ----
__device__ __forceinline__ void garrive(int g) {
    __syncthreads();
    if (threadIdx.x == 0) {
        asm volatile("red.release.gpu.add.u32 [%0], %1;" :: "l"(&g_cnt2[g * 32]), "r"(1u) : "memory");
    }
}
__device__ __forceinline__ void gwait(int g, unsigned target) {
    if (threadIdx.x == 0) {
        unsigned v;
        do {
            asm volatile("ld.acquire.gpu.u32 %0, [%1];" : "=r"(v) : "l"(&g_cnt2[g * 32]) : "memory");
        } while (v < target);
    }
    __syncthreads();
}

// Persistent recurrence with WARP-SPECIALIZED xW producers (no separate GEMM).
// 128 CTAs = (b-half bh) x (64 col-groups cg: 8 hidden units = 32 gate cols).
// 384 threads = 8 rec warps (R12 code path) + 4 producer warps (1 per SMSP).
// Producers, during step t's compute window, stage xT[t+1] slice into xs and
// accumulate the xW partial tile [32c][32b] into a 2-slot smem ring — fully
// OFF the barrier critical path (depends only on x). Consumer's fused reduce
// adds ring[t&1] + 8 rec partials + bias.
// Rec h staging uses a 32-row warp-local buffer (A/B reuse with syncwarp).
// Smem floats: Us 16384 + Ws 8192 + hs 8192 + xs 8192 + part 8192 + ring 2048
//            = 51200 floats = 200 KB.
#define REC_SMEM_FLOATS (16384 + 8192 + 8192 + 8192 + 8192 + 2048)

__global__ __launch_bounds__(384, 1) void lstm_rec_k(float* __restrict__ out,
                                                     const float* __restrict__ bias) {
    extern __shared__ float sm[];
    float* Us   = sm;            // [512][32]
    float* Ws   = sm + 16384;    // [256][32]
    float* hs   = sm + 24576;    // [8 rec warps][32][32]
    float* xs   = sm + 32768;    // [256][32]  next-step x slice (k-major)
    float* part = sm + 40960;    // [8][32c][32b]
    float* ring = sm + 49152;    // [2][32c][32b]

    const int n   = blockIdx.x;
    const int tid = threadIdx.x;
    const int bh  = n & 1;
    const int cg  = n >> 1;
    const int wid = tid >> 5;
    const int L   = tid & 31;
    const bool isrec = (wid < 8);
    // rec compute roles
    const int w   = wid;               // rec warp k-range owner
    const int b0  = (L & 3) * 8;
    const int c0  = (L >> 2) * 4;
    // producer roles (wid 8..11)
    const int pw  = wid - 8;
    const int pc  = 8 * pw + (L >> 2); // producer column (1 per lane-group)
    const int pb0 = (L & 3) * 8;
    const int pt  = tid - 256;         // 0..127
    // update role
    const int ub  = tid & 31;
    const int ujj = tid >> 5;          // 0..7 for tid<256
    const int jbase = cg * 8;

    // resident U slice [512][32] and W slice [256][32]
    {
        const float4* Usrc = (const float4*)(g_Up + (size_t)cg * 16384);
        float4* Udst = (float4*)Us;
        for (int i = tid; i < 4096; i += 384) Udst[i] = Usrc[i];
        const float4* Wsrc = (const float4*)(g_Wp + (size_t)cg * 8192);
        float4* Wdst = (float4*)Ws;
        for (int i = tid; i < 2048; i += 384) Wdst[i] = Wsrc[i];
    }

    float bj0 = 0.f, bj1 = 0.f, bj2 = 0.f, bj3 = 0.f;
    if (tid < 256) {
        bj0 = bias[0 * Hsz + jbase + ujj];
        bj1 = bias[1 * Hsz + jbase + ujj];
        bj2 = bias[2 * Hsz + jbase + ujj];
        bj3 = bias[3 * Hsz + jbase + ujj];
        // zero h parity 0 (this CTA's slice)
        g_h[(jbase + ujj) * 64 + bh * 32 + ub] = 0.0f;
    }
    float creg = 0.0f, hreg = 0.0f;

    __syncthreads();   // Ws/Us visible before prologue produce

    // ---- prologue: produce ring slot 0 (t = 0) ----
    if (!isrec) {
        // stage xT[0] slice into xs
        const float* xsrc = g_xT + 0 + (size_t)bh * 32;
        float4 tv[16];
#pragma unroll
        for (int m = 0; m < 16; ++m) {
            int idx = pt + 128 * m; int k = idx >> 3, q = idx & 7;
            tv[m] = __ldg((const float4*)(xsrc + (size_t)k * 64) + q);
        }
#pragma unroll
        for (int m = 0; m < 16; ++m) {
            int idx = pt + 128 * m; int k = idx >> 3, q = idx & 7;
            *(float4*)&xs[k * 32 + q * 4] = tv[m];
        }
        asm volatile("bar.sync 7, 128;" ::: "memory");
        u64 pacc[4] = {0ull, 0ull, 0ull, 0ull};
        const float* wsp = Ws + pc;
#pragma unroll 8
        for (int k = 0; k < 256; ++k) {
            ulonglong2 ha = *(const ulonglong2*)&xs[k * 32 + pb0];
            ulonglong2 hb = *(const ulonglong2*)&xs[k * 32 + pb0 + 4];
            u64 ud = dup2(wsp[k * 32]);
            pacc[0] = ffma2(ha.x, ud, pacc[0]);
            pacc[1] = ffma2(ha.y, ud, pacc[1]);
            pacc[2] = ffma2(hb.x, ud, pacc[2]);
            pacc[3] = ffma2(hb.y, ud, pacc[3]);
        }
        float* rp = ring + pc * 32 + pb0;
        *(ulonglong2*)rp       = make_ulonglong2(pacc[0], pacc[1]);
        *(ulonglong2*)(rp + 4) = make_ulonglong2(pacc[2], pacc[3]);
    }

    unsigned target = GRP;
    garrive(bh);

    float* hw = hs + w * 1024;         // rec warp staging [32][32]

    for (int step = 0; step < Tsz; ++step) {
        const int p = step & 1;
        const float* hq = g_h + p * (Hsz * Bsz) + bh * 32;   // row stride 64

        gwait(bh, target);
        target += GRP;

        u64 acc[16];
#pragma unroll
        for (int j = 0; j < 16; ++j) acc[j] = 0ull;

        if (isrec) {
            // ---- stage half A (rows [64w, 64w+32)) ----
            float4 pv[8];
#pragma unroll
            for (int m = 0; m < 8; ++m) {
                int idx = L + 32 * m; int r = idx >> 3, q = idx & 7;
                pv[m] = __ldcg((const float4*)(hq + (w * 64 + r) * 64) + q);
            }
#pragma unroll
            for (int m = 0; m < 8; ++m) {
                int idx = L + 32 * m; int r = idx >> 3, q = idx & 7;
                *(float4*)&hw[r * 32 + q * 4] = pv[m];
            }
            // LDG half B in flight under compute A
            float4 pw4[8];
#pragma unroll
            for (int m = 0; m < 8; ++m) {
                int idx = L + 32 * m; int r = 32 + (idx >> 3), q = idx & 7;
                pw4[m] = __ldcg((const float4*)(hq + (w * 64 + r) * 64) + q);
            }
            __syncwarp();

            // ---- compute half A ----
#pragma unroll 16
            for (int i = 0; i < 32; ++i) {
                ulonglong2 hA = *(const ulonglong2*)&hw[i * 32 + b0];
                ulonglong2 hB = *(const ulonglong2*)&hw[i * 32 + b0 + 4];
                float4 uq = *(const float4*)&Us[(w * 64 + i) * 32 + c0];
                u64 u0 = dup2(uq.x), u1 = dup2(uq.y), u2 = dup2(uq.z), u3 = dup2(uq.w);
                acc[0]  = ffma2(hA.x, u0, acc[0]);
                acc[1]  = ffma2(hA.y, u0, acc[1]);
                acc[2]  = ffma2(hB.x, u0, acc[2]);
                acc[3]  = ffma2(hB.y, u0, acc[3]);
                acc[4]  = ffma2(hA.x, u1, acc[4]);
                acc[5]  = ffma2(hA.y, u1, acc[5]);
                acc[6]  = ffma2(hB.x, u1, acc[6]);
                acc[7]  = ffma2(hB.y, u1, acc[7]);
                acc[8]  = ffma2(hA.x, u2, acc[8]);
                acc[9]  = ffma2(hA.y, u2, acc[9]);
                acc[10] = ffma2(hB.x, u2, acc[10]);
                acc[11] = ffma2(hB.y, u2, acc[11]);
                acc[12] = ffma2(hA.x, u3, acc[12]);
                acc[13] = ffma2(hA.y, u3, acc[13]);
                acc[14] = ffma2(hB.x, u3, acc[14]);
                acc[15] = ffma2(hB.y, u3, acc[15]);
            }
            __syncwarp();   // all lanes done reading buffer before overwrite

            // ---- stage half B into same buffer ----
#pragma unroll
            for (int m = 0; m < 8; ++m) {
                int idx = L + 32 * m; int r = idx >> 3, q = idx & 7;
                *(float4*)&hw[r * 32 + q * 4] = pw4[m];
            }
            __syncwarp();

            // ---- compute half B ----
#pragma unroll 16
            for (int i = 0; i < 32; ++i) {
                ulonglong2 hA = *(const ulonglong2*)&hw[i * 32 + b0];
                ulonglong2 hB = *(const ulonglong2*)&hw[i * 32 + b0 + 4];
                float4 uq = *(const float4*)&Us[(w * 64 + 32 + i) * 32 + c0];
                u64 u0 = dup2(uq.x), u1 = dup2(uq.y), u2 = dup2(uq.z), u3 = dup2(uq.w);
                acc[0]  = ffma2(hA.x, u0, acc[0]);
                acc[1]  = ffma2(hA.y, u0, acc[1]);
                acc[2]  = ffma2(hB.x, u0, acc[2]);
                acc[3]  = ffma2(hB.y, u0, acc[3]);
                acc[4]  = ffma2(hA.x, u1, acc[4]);
                acc[5]  = ffma2(hA.y, u1, acc[5]);
                acc[6]  = ffma2(hB.x, u1, acc[6]);
                acc[7]  = ffma2(hB.y, u1, acc[7]);
                acc[8]  = ffma2(hA.x, u2, acc[8]);
                acc[9]  = ffma2(hA.y, u2, acc[9]);
                acc[10] = ffma2(hB.x, u2, acc[10]);
                acc[11] = ffma2(hB.y, u2, acc[11]);
                acc[12] = ffma2(hA.x, u3, acc[12]);
                acc[13] = ffma2(hA.y, u3, acc[13]);
                acc[14] = ffma2(hB.x, u3, acc[14]);
                acc[15] = ffma2(hB.y, u3, acc[15]);
            }

            // per-warp partial tile [32c][32b]
#pragma unroll
            for (int j = 0; j < 4; ++j) {
                float* pp = part + w * 1024 + (c0 + j) * 32 + b0;
                *(ulonglong2*)pp       = make_ulonglong2(acc[4 * j + 0], acc[4 * j + 1]);
                *(ulonglong2*)(pp + 4) = make_ulonglong2(acc[4 * j + 2], acc[4 * j + 3]);
            }
        } else if (step + 1 < Tsz) {
            // ===== producers: build xW[t+1] into ring slot (step+1)&1 =====
            const int tn = step + 1;
            const float* xsrc = g_xT + (size_t)tn * (Dsz * Bsz) + bh * 32;
            float4 tv[16];
#pragma unroll
            for (int m = 0; m < 16; ++m) {
                int idx = pt + 128 * m; int k = idx >> 3, q = idx & 7;
                tv[m] = __ldg((const float4*)(xsrc + (size_t)k * 64) + q);
            }
#pragma unroll
            for (int m = 0; m < 16; ++m) {
                int idx = pt + 128 * m; int k = idx >> 3, q = idx & 7;
                *(float4*)&xs[k * 32 + q * 4] = tv[m];
            }
            asm volatile("bar.sync 7, 128;" ::: "memory");
            u64 pacc[4] = {0ull, 0ull, 0ull, 0ull};
            const float* wsp = Ws + pc;
#pragma unroll 8
            for (int k = 0; k < 256; ++k) {
                ulonglong2 ha = *(const ulonglong2*)&xs[k * 32 + pb0];
                ulonglong2 hb = *(const ulonglong2*)&xs[k * 32 + pb0 + 4];
                u64 ud = dup2(wsp[k * 32]);
                pacc[0] = ffma2(ha.x, ud, pacc[0]);
                pacc[1] = ffma2(ha.y, ud, pacc[1]);
                pacc[2] = ffma2(hb.x, ud, pacc[2]);
                pacc[3] = ffma2(hb.y, ud, pacc[3]);
            }
            float* rp = ring + (tn & 1) * 1024 + pc * 32 + pb0;
            *(ulonglong2*)rp       = make_ulonglong2(pacc[0], pacc[1]);
            *(ulonglong2*)(rp + 4) = make_ulonglong2(pacc[2], pacc[3]);
        }
        __syncthreads();

        // FUSED reduce + update: thread (b = ub, j = jbase + ujj), tid < 256
        if (tid < 256) {
            const float* rg = ring + (step & 1) * 1024;
            float v[4];
#pragma unroll
            for (int g = 0; g < 4; ++g) {
                const float* pp = part + (g * 8 + ujj) * 32 + ub;
                float s = rg[(g * 8 + ujj) * 32 + ub];
#pragma unroll
                for (int ww = 0; ww < 8; ++ww) s += pp[ww * 1024];
                v[g] = s;
            }
            float ig = 1.0f / (1.0f + __expf(-(v[0] + bj0)));
            float fg = 1.0f / (1.0f + __expf(-(v[1] + bj1)));
            float gg = tanhf(v[2] + bj2);
            float og = 1.0f / (1.0f + __expf(-(v[3] + bj3)));
            creg = fg * creg + ig * gg;
            hreg = og * tanhf(creg);
            __stcg(&g_h[(p ^ 1) * (Hsz * Bsz) + (jbase + ujj) * 64 + bh * 32 + ub], hreg);
        }

        garrive(bh);
    }

    if (tid < 256) {
        out[(bh * 32 + ub) * Hsz + jbase + ujj] = hreg;
        out[Bsz * Hsz + (bh * 32 + ub) * Hsz + jbase + ujj] = creg;
    }
}

extern "C" void kernel_launch(void* const* d_in, const int* in_sizes, int n_in,
                              void* d_out, int out_size) {
    const float* x    = (const float*)d_in[0];
    const float* W    = (const float*)d_in[1];
    const float* U    = (const float*)d_in[2];
    const float* bias = (const float*)d_in[3];
    float* out = (float*)d_out;
    (void)in_sizes; (void)n_in; (void)out_size;

    static int smem_set = 0;
    if (!smem_set) {
        cudaFuncSetAttribute(lstm_rec_k, cudaFuncAttributeMaxDynamicSharedMemorySize,
                             REC_SMEM_FLOATS * 4);
        smem_set = 1;
    }

    transpose_x_k<<<131072, 256>>>(x);
    pack_U_k<<<2048, 512>>>(U);
    pack_W_k<<<1024, 512>>>(W);
    reset_bar_k<<<1, 64>>>();
    lstm_rec_k<<<NB, 384, REC_SMEM_FLOATS * 4>>>(out, bias);
}

// round 17
// speedup vs baseline: 1.6951x; 1.6951x over previous
#include <cuda_runtime.h>
#include <math.h>

#define Bsz 64
#define Tsz 2048
#define Dsz 256
#define Hsz 512
#define Gsz 2048
#define NB  128
#define GRP 64

typedef unsigned long long u64;

// ---- packed fp32x2 helpers (Blackwell FFMA2, PTX-only) ----
__device__ __forceinline__ u64 ffma2(u64 a, u64 b, u64 c) {
    u64 d;
    asm("fma.rn.f32x2 %0, %1, %2, %3;" : "=l"(d) : "l"(a), "l"(b), "l"(c));
    return d;
}
__device__ __forceinline__ u64 dup2(float x) {
    u64 d;
    asm("mov.b64 %0, {%1, %1};" : "=l"(d) : "r"(__float_as_uint(x)));
    return d;
}
__device__ __forceinline__ unsigned f2tf32(float v) {
    unsigned r;
    asm("cvt.rna.tf32.f32 %0, %1;" : "=r"(r) : "f"(v));
    return r;
}

// Scratch (device globals)
__device__ float g_xw[(size_t)Tsz * Gsz * Bsz];    // [t][col][b]  1 GiB
__device__ float g_WT[Gsz * Dsz];                  // [col][k] tf32-rounded, 2 MB
__device__ float g_Up[64 * Hsz * 32];              // [cg][k][c]   4 MB
__device__ float g_h[2 * Hsz * Bsz];               // [parity][j][b]
__device__ unsigned g_cnt2[64];                    // 2 counters, 128B apart

__global__ void reset_bar_k() { if (threadIdx.x < 64) g_cnt2[threadIdx.x] = 0u; }

// g_Up[cg][k][c] = U[k][gate*512 + cg*8 + jj], c = gate*8 + jj  (32 cols per cg)
__global__ void pack_U_k(const float* __restrict__ U) {
    int idx = blockIdx.x * blockDim.x + threadIdx.x;   // 2^20 total
    int c  = idx & 31;
    int k  = (idx >> 5) & (Hsz - 1);
    int cg = idx >> 14;
    g_Up[idx] = U[k * Gsz + (c >> 3) * Hsz + cg * 8 + (c & 7)];
}

// g_WT[col][k] = tf32(W[k][col])
__global__ void pack_WT_k(const float* __restrict__ W) {
    int idx = blockIdx.x * blockDim.x + threadIdx.x;   // 2^19 total
    int k   = idx & (Dsz - 1);
    int col = idx >> 8;
    unsigned r = f2tf32(W[(size_t)k * Gsz + col]);
    ((unsigned*)g_WT)[(size_t)col * Dsz + k] = r;
}

// xW GEMM with mma.sync tf32: per CTA one t, tile 128 cols x 64 b, K=256.
// A = g_WT[col][k] (tf32 pre-rounded), B = x[b][t][k] transposed + cvt in-CTA.
// 8 warps = 4 (M=32 cols) x 2 (N=32 b); per warp 2 m16 x 4 n8 frags, K in 8
// chunks of 32 (4 k8 steps each). Bias folded into accumulator init.
// Output bounced via smem for coalesced [t][col][b] stores.
// Smem union: loop As[128][36] (4608) + Bs[32][72] (2304) = 6912 f;
// store phase Ct[128][68] = 8704 f. union = 8704 floats.
__global__ __launch_bounds__(256) void gemm_tf32_k(const float* __restrict__ x,
                                                   const float* __restrict__ bias) {
    __shared__ float smem_u[8704];
    float* As = smem_u;           // [128][36]
    float* Bs = smem_u + 4608;    // [32][72]  (64 b + 8 pad)
    float* Ct = smem_u;           // [128][68] (after K loop)

    const int t   = blockIdx.y;
    const int cb  = blockIdx.x;
    const int tid = threadIdx.x;
    const int w   = tid >> 5;
    const int L   = tid & 31;
    const int wm  = w >> 1;            // 0..3  (M group: 32 cols)
    const int wn  = w & 1;             // 0..1  (N group: 32 b)
    const int gID = L >> 2;            // 0..7
    const int tg  = L & 3;             // 0..3

    // accumulators, bias-initialized: frag (m, n); c0/c1 row r, c2/c3 row r+8
    float c[2][4][4];
#pragma unroll
    for (int m = 0; m < 2; ++m) {
        int r0 = cb * 128 + 32 * wm + 16 * m + gID;
        float bv0 = __ldg(&bias[r0]);
        float bv1 = __ldg(&bias[r0 + 8]);
#pragma unroll
        for (int n = 0; n < 4; ++n) {
            c[m][n][0] = bv0; c[m][n][1] = bv0;
            c[m][n][2] = bv1; c[m][n][3] = bv1;
        }
    }

    const int bb  = tid & 63;          // batch for B staging
    const int seg = tid >> 6;          // 0..3 (8-float k segment)
    const float* xrow = x + ((size_t)bb * Tsz + t) * Dsz;

    for (int kc = 0; kc < 8; ++kc) {
        const int k0 = kc * 32;
        // ---- stage As: W^T slice [128c][32k] (coalesced, conflict-free STS.128) ----
#pragma unroll
        for (int m = 0; m < 4; ++m) {
            int f4i = tid + 256 * m;
            int cc = f4i >> 3, kq = f4i & 7;
            float4 v = __ldg((const float4*)(g_WT + (size_t)(cb * 128 + cc) * Dsz + k0 + 4 * kq));
            *(float4*)&As[cc * 36 + 4 * kq] = v;
        }
        // ---- stage Bs: x[k][b] transposed + tf32 cvt  (Bs row stride 72) ----
        {
            float4 v0 = __ldg((const float4*)(xrow + k0 + 8 * seg));
            float4 v1 = __ldg((const float4*)(xrow + k0 + 8 * seg + 4));
            float vv[8] = {v0.x, v0.y, v0.z, v0.w, v1.x, v1.y, v1.z, v1.w};
#pragma unroll
            for (int i = 0; i < 8; ++i)
                ((unsigned*)Bs)[(8 * seg + i) * 72 + bb] = f2tf32(vv[i]);
        }
        __syncthreads();

        // ---- 4 k8 steps of mma ----
#pragma unroll
        for (int ks = 0; ks < 4; ++ks) {
            const int kk = 8 * ks;
            unsigned a[2][4];
#pragma unroll
            for (int m = 0; m < 2; ++m) {
                int r = 32 * wm + 16 * m;
                a[m][0] = *(const unsigned*)&As[(r + gID) * 36 + kk + tg];
                a[m][1] = *(const unsigned*)&As[(r + gID + 8) * 36 + kk + tg];
                a[m][2] = *(const unsigned*)&As[(r + gID) * 36 + kk + tg + 4];
                a[m][3] = *(const unsigned*)&As[(r + gID + 8) * 36 + kk + tg + 4];
            }
            unsigned b[4][2];
#pragma unroll
            for (int n = 0; n < 4; ++n) {
                int bc = 32 * wn + 8 * n + gID;
                b[n][0] = *(const unsigned*)&Bs[(kk + tg) * 72 + bc];
                b[n][1] = *(const unsigned*)&Bs[(kk + tg + 4) * 72 + bc];
            }
#pragma unroll
            for (int m = 0; m < 2; ++m)
#pragma unroll
                for (int n = 0; n < 4; ++n) {
                    asm volatile(
                        "mma.sync.aligned.m16n8k8.row.col.f32.tf32.tf32.f32 "
                        "{%0,%1,%2,%3}, {%4,%5,%6,%7}, {%8,%9}, {%0,%1,%2,%3};"
                        : "+f"(c[m][n][0]), "+f"(c[m][n][1]),
                          "+f"(c[m][n][2]), "+f"(c[m][n][3])
                        : "r"(a[m][0]), "r"(a[m][1]), "r"(a[m][2]), "r"(a[m][3]),
                          "r"(b[n][0]), "r"(b[n][1]));
                }
        }
        __syncthreads();
    }

    // ---- store frags to Ct [128][68], then coalesced STG ----
#pragma unroll
    for (int m = 0; m < 2; ++m) {
        int r = 32 * wm + 16 * m + gID;
#pragma unroll
        for (int n = 0; n < 4; ++n) {
            int bcol = 32 * wn + 8 * n + 2 * tg;
            *(float2*)&Ct[r * 68 + bcol]       = make_float2(c[m][n][0], c[m][n][1]);
            *(float2*)&Ct[(r + 8) * 68 + bcol] = make_float2(c[m][n][2], c[m][n][3]);
        }
    }
    __syncthreads();
#pragma unroll
    for (int m = 0; m < 8; ++m) {
        int f4i = tid + 256 * m;
        int row = f4i >> 4, q = f4i & 15;
        float4 v = *(const float4*)&Ct[row * 68 + 4 * q];
        *(float4*)&g_xw[((size_t)t * Gsz + cb * 128 + row) * 64 + 4 * q] = v;
    }
}

// ---- dual 64-CTA group barriers: release-REDG arrive + acquire-poll wait ----
__device__ __forceinline__ void garrive(int g) {
    __syncthreads();
    if (threadIdx.x == 0) {
        asm volatile("red.release.gpu.add.u32 [%0], %1;" :: "l"(&g_cnt2[g * 32]), "r"(1u) : "memory");
    }
}
__device__ __forceinline__ void gwait(int g, unsigned target) {
    if (threadIdx.x == 0) {
        unsigned v;
        do {
            asm volatile("ld.acquire.gpu.u32 %0, [%1];" : "=r"(v) : "l"(&g_cnt2[g * 32]) : "memory");
        } while (v < target);
    }
    __syncthreads();
}

// Persistent recurrence — R12 verbatim (best-known configuration).
#define REC_SMEM_FLOATS (16384 + 16384 + 8192)

__global__ __launch_bounds__(256, 1) void lstm_rec_k(float* __restrict__ out) {
    extern __shared__ float sm[];
    float* Us   = sm;            // [512][32]
    float* hs   = sm + 16384;    // [w][64][32]
    float* part = sm + 32768;    // [w][32c][32b]

    const int n   = blockIdx.x;
    const int tid = threadIdx.x;
    const int bh  = n & 1;
    const int cg  = n >> 1;
    const int w   = tid >> 5;
    const int L   = tid & 31;
    const int b0  = (L & 3) * 8;
    const int c0  = (L >> 2) * 4;
    const int ub  = tid & 31;          // update role: batch within half
    const int ujj = tid >> 5;          // update role: hidden-within-cg 0..7
    const int jbase = cg * 8;

    // resident U slice [512][32]
    {
        const float4* Usrc = (const float4*)(g_Up + (size_t)cg * 16384);
        float4* Udst = (float4*)Us;
        for (int i = tid; i < 4096; i += 256) Udst[i] = Usrc[i];
    }

    // zero h parity 0 (this CTA's slice)
    g_h[(jbase + ujj) * 64 + bh * 32 + ub] = 0.0f;
    float creg = 0.0f, hreg = 0.0f;

    unsigned target = GRP;
    garrive(bh);

    float* hw = hs + w * 2048;         // this warp's staging area [64][32]

    for (int step = 0; step < Tsz; ++step) {
        const int p = step & 1;
        const float* hq = g_h + p * (Hsz * Bsz) + bh * 32;   // row stride 64

        // xW loads in flight across the barrier wait
        const size_t xbase = (size_t)step * Gsz;
        float xg0 = __ldcs(&g_xw[(xbase + 0 * Hsz + jbase + ujj) * 64 + bh * 32 + ub]);
        float xg1 = __ldcs(&g_xw[(xbase + 1 * Hsz + jbase + ujj) * 64 + bh * 32 + ub]);
        float xg2 = __ldcs(&g_xw[(xbase + 2 * Hsz + jbase + ujj) * 64 + bh * 32 + ub]);
        float xg3 = __ldcs(&g_xw[(xbase + 3 * Hsz + jbase + ujj) * 64 + bh * 32 + ub]);

        gwait(bh, target);
        target += GRP;

        u64 acc[16];
#pragma unroll
        for (int j = 0; j < 16; ++j) acc[j] = 0ull;

        // ---- stage half A (rows [64w, 64w+32)) ----
        float4 pv[8];
#pragma unroll
        for (int m = 0; m < 8; ++m) {
            int idx = L + 32 * m; int r = idx >> 3, q = idx & 7;
            pv[m] = __ldcg((const float4*)(hq + (w * 64 + r) * 64) + q);
        }
#pragma unroll
        for (int m = 0; m < 8; ++m) {
            int idx = L + 32 * m; int r = idx >> 3, q = idx & 7;
            *(float4*)&hw[r * 32 + q * 4] = pv[m];
        }
        // issue LDG for half B (latency hides under compute A)
        float4 pw[8];
#pragma unroll
        for (int m = 0; m < 8; ++m) {
            int idx = L + 32 * m; int r = 32 + (idx >> 3), q = idx & 7;
            pw[m] = __ldcg((const float4*)(hq + (w * 64 + r) * 64) + q);
        }
        __syncwarp();

        // ---- compute half A ----
#pragma unroll 16
        for (int i = 0; i < 32; ++i) {
            ulonglong2 hA = *(const ulonglong2*)&hw[i * 32 + b0];
            ulonglong2 hB = *(const ulonglong2*)&hw[i * 32 + b0 + 4];
            float4 uq = *(const float4*)&Us[(w * 64 + i) * 32 + c0];
            u64 u0 = dup2(uq.x), u1 = dup2(uq.y), u2 = dup2(uq.z), u3 = dup2(uq.w);
            acc[0]  = ffma2(hA.x, u0, acc[0]);
            acc[1]  = ffma2(hA.y, u0, acc[1]);
            acc[2]  = ffma2(hB.x, u0, acc[2]);
            acc[3]  = ffma2(hB.y, u0, acc[3]);
            acc[4]  = ffma2(hA.x, u1, acc[4]);
            acc[5]  = ffma2(hA.y, u1, acc[5]);
            acc[6]  = ffma2(hB.x, u1, acc[6]);
            acc[7]  = ffma2(hB.y, u1, acc[7]);
            acc[8]  = ffma2(hA.x, u2, acc[8]);
            acc[9]  = ffma2(hA.y, u2, acc[9]);
            acc[10] = ffma2(hB.x, u2, acc[10]);
            acc[11] = ffma2(hB.y, u2, acc[11]);
            acc[12] = ffma2(hA.x, u3, acc[12]);
            acc[13] = ffma2(hA.y, u3, acc[13]);
            acc[14] = ffma2(hB.x, u3, acc[14]);
            acc[15] = ffma2(hB.y, u3, acc[15]);
        }

        // ---- stage half B ----
#pragma unroll
        for (int m = 0; m < 8; ++m) {
            int idx = L + 32 * m; int r = 32 + (idx >> 3), q = idx & 7;
            *(float4*)&hw[r * 32 + q * 4] = pw[m];
        }
        __syncwarp();

        // ---- compute half B ----
#pragma unroll 16
        for (int i = 32; i < 64; ++i) {
            ulonglong2 hA = *(const ulonglong2*)&hw[i * 32 + b0];
            ulonglong2 hB = *(const ulonglong2*)&hw[i * 32 + b0 + 4];
            float4 uq = *(const float4*)&Us[(w * 64 + i) * 32 + c0];
            u64 u0 = dup2(uq.x), u1 = dup2(uq.y), u2 = dup2(uq.z), u3 = dup2(uq.w);
            acc[0]  = ffma2(hA.x, u0, acc[0]);
            acc[1]  = ffma2(hA.y, u0, acc[1]);
            acc[2]  = ffma2(hB.x, u0, acc[2]);
            acc[3]  = ffma2(hB.y, u0, acc[3]);
            acc[4]  = ffma2(hA.x, u1, acc[4]);
            acc[5]  = ffma2(hA.y, u1, acc[5]);
            acc[6]  = ffma2(hB.x, u1, acc[6]);
            acc[7]  = ffma2(hB.y, u1, acc[7]);
            acc[8]  = ffma2(hA.x, u2, acc[8]);
            acc[9]  = ffma2(hA.y, u2, acc[9]);
            acc[10] = ffma2(hB.x, u2, acc[10]);
            acc[11] = ffma2(hB.y, u2, acc[11]);
            acc[12] = ffma2(hA.x, u3, acc[12]);
            acc[13] = ffma2(hA.y, u3, acc[13]);
            acc[14] = ffma2(hB.x, u3, acc[14]);
            acc[15] = ffma2(hB.y, u3, acc[15]);
        }

        // per-warp partial tile [32c][32b] (own region)
#pragma unroll
        for (int j = 0; j < 4; ++j) {
            float* pp = part + w * 1024 + (c0 + j) * 32 + b0;
            *(ulonglong2*)pp       = make_ulonglong2(acc[4 * j + 0], acc[4 * j + 1]);
            *(ulonglong2*)(pp + 4) = make_ulonglong2(acc[4 * j + 2], acc[4 * j + 3]);
        }
        __syncthreads();

        // FUSED reduce + update: thread (b = ub, j = jbase + ujj) sums its own
        // 8 warp-partials per gate (bank = ub -> conflict-free scalar LDS)
        float v[4];
#pragma unroll
        for (int g = 0; g < 4; ++g) {
            const float* pp = part + (g * 8 + ujj) * 32 + ub;
            float s = pp[0];
#pragma unroll
            for (int ww = 1; ww < 8; ++ww) s += pp[ww * 1024];
            v[g] = s;
        }
        float ig = 1.0f / (1.0f + __expf(-(v[0] + xg0)));
        float fg = 1.0f / (1.0f + __expf(-(v[1] + xg1)));
        float gg = tanhf(v[2] + xg2);
        float og = 1.0f / (1.0f + __expf(-(v[3] + xg3)));
        creg = fg * creg + ig * gg;
        hreg = og * tanhf(creg);
        __stcg(&g_h[(p ^ 1) * (Hsz * Bsz) + (jbase + ujj) * 64 + bh * 32 + ub], hreg);

        garrive(bh);
    }

    out[(bh * 32 + ub) * Hsz + jbase + ujj] = hreg;
    out[Bsz * Hsz + (bh * 32 + ub) * Hsz + jbase + ujj] = creg;
}

extern "C" void kernel_launch(void* const* d_in, const int* in_sizes, int n_in,
                              void* d_out, int out_size) {
    const float* x    = (const float*)d_in[0];
    const float* W    = (const float*)d_in[1];
    const float* U    = (const float*)d_in[2];
    const float* bias = (const float*)d_in[3];
    float* out = (float*)d_out;
    (void)in_sizes; (void)n_in; (void)out_size;

    static int smem_set = 0;
    if (!smem_set) {
        cudaFuncSetAttribute(lstm_rec_k, cudaFuncAttributeMaxDynamicSharedMemorySize,
                             REC_SMEM_FLOATS * 4);
        smem_set = 1;
    }

    pack_U_k<<<2048, 512>>>(U);
    pack_WT_k<<<1024, 512>>>(W);
    dim3 g(16, Tsz);
    gemm_tf32_k<<<g, 256>>>(x, bias);
    reset_bar_k<<<1, 64>>>();
    lstm_rec_k<<<NB, 256, REC_SMEM_FLOATS * 4>>>(out);
}